// round 2
// baseline (speedup 1.0000x reference)
#include <cuda_runtime.h>

#define NRAYS_EXPECTED 65536
#define SCOARSE 256
#define SFINE   128
#define WARPS_PER_BLOCK 8

// log10 step of the coarse grid: both segments are exactly uniform with step 1/128
#define ZSTEP 0.0078125f
// ALPHA_RW / S = 1e-4 / 256
#define ALPHA_OVER_S 3.90625e-7f
#define LN10 2.302585093f

__device__ __forceinline__ float fast_exp(float x)   { return __expf(x); }
__device__ __forceinline__ float fast_exp10(float x) { return __expf(x * LN10); }

// mipnerf360 contraction (INNER = 1)
__device__ __forceinline__ void contract(float x, float y, float z,
                                         float& sx, float& sy, float& sz) {
    float n2 = x * x + y * y + z * z;
    float n  = sqrtf(n2);
    n = fmaxf(n, 1e-8f);
    if (n <= 1.0f) {
        sx = x; sy = y; sz = z;
    } else {
        float inv = 1.0f / n;
        float f = (2.0f - inv) * inv;
        sx = x * f; sy = y * f; sz = z * f;
    }
}

__global__ __launch_bounds__(WARPS_PER_BLOCK * 32)
void nerf_render_kernel(const float* __restrict__ rays_o,
                        const float* __restrict__ rays_d,
                        const float* __restrict__ bg_color,
                        float* __restrict__ out,
                        int N)
{
    const unsigned FULL = 0xffffffffu;
    const int lane   = threadIdx.x & 31;
    const int wlocal = threadIdx.x >> 5;
    const int ray    = blockIdx.x * WARPS_PER_BLOCK + wlocal;
    if (ray >= N) return;

    __shared__ float sW[WARPS_PER_BLOCK][SCOARSE];   // coarse weights
    __shared__ float sC[WARPS_PER_BLOCK][SCOARSE];   // cdf
    __shared__ float sZ[WARPS_PER_BLOCK][SFINE];     // fine zlog samples

    // ---- ray data (broadcast loads) ----
    float ox = rays_o[ray * 3 + 0];
    float oy = rays_o[ray * 3 + 1];
    float oz = rays_o[ray * 3 + 2];
    float dx = rays_d[ray * 3 + 0];
    float dy = rays_d[ray * 3 + 1];
    float dz = rays_d[ray * 3 + 2];
    {
        float inv = rsqrtf(dx * dx + dy * dy + dz * dz);
        dx *= inv; dy *= inv; dz *= inv;
    }

    // =====================================================================
    // COARSE PASS: 256 samples, 8 contiguous per lane
    // =====================================================================
    float om8[8], al8[8];
    float chunkprod = 1.0f;
#pragma unroll
    for (int j = 0; j < 8; ++j) {
        int k = lane * 8 + j;
        float zl = (float)(k - 128) * ZSTEP;     // exact coarse grid
        float z  = fast_exp10(zl);
        float x = ox + dx * z, y = oy + dy * z, zz = oz + dz * z;
        float sx, sy, sz;
        contract(x, y, zz, sx, sy, sz);
        float ss  = sx * sx + sy * sy + sz * sz;
        float sig = 25.0f * fast_exp(-4.0f * ss);
        float dlt = (k == SCOARSE - 1) ? 0.0f : ZSTEP;
        float o   = fast_exp(-sig * dlt);        // 1 - alpha
        om8[j] = o;
        al8[j] = 1.0f - o;
        chunkprod *= o;
    }
    // warp inclusive product scan of chunk products
    float incl = chunkprod;
#pragma unroll
    for (int off = 1; off < 32; off <<= 1) {
        float v = __shfl_up_sync(FULL, incl, off);
        if (lane >= off) incl *= v;
    }
    float trans = __shfl_up_sync(FULL, incl, 1);
    if (lane == 0) trans = 1.0f;
#pragma unroll
    for (int j = 0; j < 8; ++j) {
        sW[wlocal][lane * 8 + j] = al8[j] * trans;
        trans *= om8[j];
    }
    __syncwarp();

    // =====================================================================
    // REWEIGHT (maxblur + alpha floor; the 0.5 segment scale cancels
    // bit-exactly under normalization) + CDF
    // =====================================================================
    float wr8[8];
    float csum = 0.0f;
#pragma unroll
    for (int j = 0; j < 8; ++j) {
        int k = lane * 8 + j;
        float wm = sW[wlocal][k];
        float wl = (k == 0)            ? 0.0f : sW[wlocal][k - 1];
        float wh = (k == SCOARSE - 1)  ? 0.0f : sW[wlocal][k + 1];
        float v = 0.5f * (fmaxf(wl, wm) + fmaxf(wm, wh)) + ALPHA_OVER_S;
        wr8[j] = v;
        csum += v;
    }
    float incs = csum;
#pragma unroll
    for (int off = 1; off < 32; off <<= 1) {
        float v = __shfl_up_sync(FULL, incs, off);
        if (lane >= off) incs += v;
    }
    float total = __shfl_sync(FULL, incs, 31);
    float run   = __shfl_up_sync(FULL, incs, 1);
    if (lane == 0) run = 0.0f;
    float inv_total = 1.0f / total;
#pragma unroll
    for (int j = 0; j < 8; ++j) {
        run += wr8[j];
        sC[wlocal][lane * 8 + j] = run * inv_total;
    }
    __syncwarp();

    // =====================================================================
    // IMPORTANCE SAMPLING: 128 stratified u, inverse-CDF, 4 per lane
    // =====================================================================
    const long long N3   = (long long)N * 3;
    const long long NWF  = (long long)N * SFINE;
    float* __restrict__ out_img = out;
    float* __restrict__ out_wf  = out + N3;
    float* __restrict__ out_zv  = out + N3 + NWF;
    float* __restrict__ out_inv = out + N3 + 2 * NWF;

    const float* cdf = sC[wlocal];
#pragma unroll
    for (int j = 0; j < 4; ++j) {
        int i = lane * 4 + j;
        float u = ((float)i + 0.5f) * (1.0f / 128.0f);
        // upper_bound: first idx with cdf[idx] > u  (== searchsorted side='right')
        int lo = 0, hi = SCOARSE;
        while (lo < hi) {
            int mid = (lo + hi) >> 1;
            if (cdf[mid] > u) hi = mid; else lo = mid + 1;
        }
        int below = min(max(lo - 1, 0), SCOARSE - 1);
        int above = min(lo, SCOARSE - 1);
        float c0 = cdf[below], c1 = cdf[above];
        float b0 = (float)(below - 128) * ZSTEP;
        float b1 = (float)(above - 128) * ZSTEP;
        float dn = c1 - c0;
        dn = (dn < 1e-8f) ? 1.0f : dn;
        float t = (u - c0) / dn;
        t = fminf(fmaxf(t, 0.0f), 1.0f);
        float zlf = b0 + t * (b1 - b0);
        sZ[wlocal][i] = zlf;
        out_zv[(long long)ray * SFINE + i] = (zlf + 1.0f) * 0.5f;  // (zlf-lo)/(hi-lo)
    }
    __syncwarp();

    // =====================================================================
    // FINE PASS: 128 samples, 4 contiguous per lane
    // =====================================================================
    float om4[4], al4[4], zf4[4];
    float rr[4], rg[4], rb[4];
    float cp = 1.0f;
#pragma unroll
    for (int j = 0; j < 4; ++j) {
        int i = lane * 4 + j;
        float zlf = sZ[wlocal][i];
        float dlt = (i == SFINE - 1) ? 0.0f : (sZ[wlocal][i + 1] - zlf);
        float z = fast_exp10(zlf);
        zf4[j] = z;
        float x = ox + dx * z, y = oy + dy * z, zz = oz + dz * z;
        float sx, sy, sz;
        contract(x, y, zz, sx, sy, sz);
        float ss  = sx * sx + sy * sy + sz * sz;
        float sig = 25.0f * fast_exp(-4.0f * ss);
        rr[j] = 1.0f / (1.0f + fast_exp(-(sx + 0.1f * dx)));
        rg[j] = 1.0f / (1.0f + fast_exp(-(sy + 0.1f * dy)));
        rb[j] = 1.0f / (1.0f + fast_exp(-(sz + 0.1f * dz)));
        float o = fast_exp(-sig * dlt);
        om4[j] = o;
        al4[j] = 1.0f - o;
        cp *= o;
    }
    float fincl = cp;
#pragma unroll
    for (int off = 1; off < 32; off <<= 1) {
        float v = __shfl_up_sync(FULL, fincl, off);
        if (lane >= off) fincl *= v;
    }
    float ftrans = __shfl_up_sync(FULL, fincl, 1);
    if (lane == 0) ftrans = 1.0f;

    float imr = 0.0f, img = 0.0f, imb = 0.0f, invd = 0.0f, wsum = 0.0f;
#pragma unroll
    for (int j = 0; j < 4; ++j) {
        int i = lane * 4 + j;
        float wf = al4[j] * ftrans;
        ftrans *= om4[j];
        out_wf[(long long)ray * SFINE + i] = wf;
        imr  += wf * rr[j];
        img  += wf * rg[j];
        imb  += wf * rb[j];
        invd += wf / zf4[j];
        wsum += wf;
    }
    // warp reductions
#pragma unroll
    for (int off = 16; off > 0; off >>= 1) {
        imr  += __shfl_xor_sync(FULL, imr,  off);
        img  += __shfl_xor_sync(FULL, img,  off);
        imb  += __shfl_xor_sync(FULL, imb,  off);
        invd += __shfl_xor_sync(FULL, invd, off);
        wsum += __shfl_xor_sync(FULL, wsum, off);
    }
    if (lane == 0) {
        float rem = 1.0f - wsum;
        out_img[(long long)ray * 3 + 0] = imr + rem * bg_color[0];
        out_img[(long long)ray * 3 + 1] = img + rem * bg_color[1];
        out_img[(long long)ray * 3 + 2] = imb + rem * bg_color[2];
        out_inv[ray] = invd;
    }
}

extern "C" void kernel_launch(void* const* d_in, const int* in_sizes, int n_in,
                              void* d_out, int out_size) {
    const float* rays_o = (const float*)d_in[0];
    const float* rays_d = (const float*)d_in[1];
    const float* bg     = (const float*)d_in[2];
    float* out = (float*)d_out;
    int N = in_sizes[0] / 3;   // rays_o is [N,3]

    int blocks = (N + WARPS_PER_BLOCK - 1) / WARPS_PER_BLOCK;
    nerf_render_kernel<<<blocks, WARPS_PER_BLOCK * 32>>>(rays_o, rays_d, bg, out, N);
}

// round 3
// speedup vs baseline: 1.6297x; 1.6297x over previous
#include <cuda_runtime.h>

#define SCOARSE 256
#define SFINE   128
#define WPB     8
#define ZSTEP   0.0078125f          // exact log10 step of coarse grid
#define ALPHA_OVER_S 3.90625e-7f    // 1e-4 / 256
#define LOG2_10 3.3219280948873623f
#define LOG2E   1.4426950408889634f

__device__ __forceinline__ float ex2(float x)  { float r; asm("ex2.approx.f32 %0, %1;"   : "=f"(r) : "f"(x)); return r; }
__device__ __forceinline__ float rcpa(float x) { float r; asm("rcp.approx.f32 %0, %1;"   : "=f"(r) : "f"(x)); return r; }
__device__ __forceinline__ float rsqa(float x) { float r; asm("rsqrt.approx.f32 %0, %1;" : "=f"(r) : "f"(x)); return r; }

__global__ __launch_bounds__(WPB * 32)
void nerf_kernel(const float* __restrict__ rays_o,
                 const float* __restrict__ rays_d,
                 const float* __restrict__ bg_color,
                 float* __restrict__ out, int N)
{
    const unsigned FULL = 0xffffffffu;
    const int lane = threadIdx.x & 31;
    const int w    = threadIdx.x >> 5;
    const int ray  = blockIdx.x * WPB + w;
    if (ray >= N) return;

    __shared__ float sB[WPB][SCOARSE];   // coarse weights, then reused for cdf

    // ---- ray setup (broadcast loads) ----
    float ox = rays_o[ray*3+0], oy = rays_o[ray*3+1], oz = rays_o[ray*3+2];
    float dx = rays_d[ray*3+0], dy = rays_d[ray*3+1], dz = rays_d[ray*3+2];
    float bgx = bg_color[0], bgy = bg_color[1], bgz = bg_color[2];
    {
        float inv = rsqa(dx*dx + dy*dy + dz*dz);
        dx *= inv; dy *= inv; dz *= inv;
    }

    // =================================================================
    // COARSE: 256 samples, 8 contiguous per lane. Only ss (=|contract|^2)
    // is needed: ss = n2 if n2<=1 else (2 - rsqrt(n2))^2.
    // =================================================================
    float om8[8], al8[8];
    float cp = 1.0f;
#pragma unroll
    for (int j = 0; j < 8; ++j) {
        int k = lane * 8 + j;
        float zl = (float)(k - 128) * ZSTEP;
        float z  = ex2(zl * LOG2_10);
        float x  = fmaf(dx, z, ox), y = fmaf(dy, z, oy), zz = fmaf(dz, z, oz);
        float n2 = fmaf(x, x, fmaf(y, y, zz * zz));
        float g  = 2.0f - rsqa(n2);
        float ss = (n2 > 1.0f) ? g * g : n2;
        float sig = 25.0f * ex2(ss * (-4.0f * LOG2E));
        float e   = (k == SCOARSE - 1) ? 0.0f : (-ZSTEP * LOG2E);
        float o   = ex2(sig * e);              // = 1 - alpha
        om8[j] = o;
        al8[j] = 1.0f - o;
        cp *= o;
    }
    // inclusive product scan of chunk products -> transmittance
    float incl = cp;
#pragma unroll
    for (int off = 1; off < 32; off <<= 1) {
        float v = __shfl_up_sync(FULL, incl, off);
        if (lane >= off) incl *= v;
    }
    float trans = __shfl_up_sync(FULL, incl, 1);
    if (lane == 0) trans = 1.0f;
#pragma unroll
    for (int j = 0; j < 8; ++j) {
        sB[w][lane * 8 + j] = al8[j] * trans;
        trans *= om8[j];
    }
    __syncwarp();

    // =================================================================
    // REWEIGHT (maxblur + floor; 0.5 segment scale cancels bit-exactly
    // under normalization) then overwrite sB with the CDF.
    // =================================================================
    float wr8[8];
    float csum = 0.0f;
#pragma unroll
    for (int j = 0; j < 8; ++j) {
        int k = lane * 8 + j;
        float wm = sB[w][k];
        float wl = (k == 0)           ? 0.0f : sB[w][k - 1];
        float wh = (k == SCOARSE - 1) ? 0.0f : sB[w][k + 1];
        float v = 0.5f * (fmaxf(wl, wm) + fmaxf(wm, wh)) + ALPHA_OVER_S;
        wr8[j] = v;
        csum += v;
    }
    float incs = csum;
#pragma unroll
    for (int off = 1; off < 32; off <<= 1) {
        float v = __shfl_up_sync(FULL, incs, off);
        if (lane >= off) incs += v;
    }
    float total = __shfl_sync(FULL, incs, 31);
    float run   = __shfl_up_sync(FULL, incs, 1);
    if (lane == 0) run = 0.0f;
    float inv_total = rcpa(total);
    __syncwarp();   // all reweight reads done before overwrite
#pragma unroll
    for (int j = 0; j < 8; ++j) {
        run += wr8[j];
        sB[w][lane * 8 + j] = run * inv_total;
    }
    __syncwarp();

    // =================================================================
    // IMPORTANCE SAMPLING: 4 stratified u per lane, branchless 8-step
    // upper-bound descent over the cdf in shared memory.
    // =================================================================
    const float* cdf = sB[w];
    float zl4[4];
#pragma unroll
    for (int j = 0; j < 4; ++j) {
        int i = lane * 4 + j;
        float u = ((float)i + 0.5f) * (1.0f / 128.0f);
        int lo = 0;
#pragma unroll
        for (int s = 128; s; s >>= 1)
            lo += (cdf[lo + s - 1] <= u) ? s : 0;
        int below = min(max(lo - 1, 0), SCOARSE - 1);
        int above = min(lo, SCOARSE - 1);
        float c0 = cdf[below], c1 = cdf[above];
        float b0 = (float)(below - 128) * ZSTEP;
        float b1 = (float)(above - 128) * ZSTEP;
        float dn = c1 - c0;
        dn = (dn < 1e-8f) ? 1.0f : dn;
        float t = (u - c0) * rcpa(dn);
        t = fminf(fmaxf(t, 0.0f), 1.0f);
        zl4[j] = fmaf(t, b1 - b0, b0);
    }

    // =================================================================
    // FINE: 4 contiguous samples per lane; deltas via regs + 1 shfl.
    // =================================================================
    float znext = __shfl_down_sync(FULL, zl4[0], 1);   // lane+1's first sample
    float hx = 0.1f * dx, hy = 0.1f * dy, hz = 0.1f * dz;

    float om4[4], al4[4], rr[4], rg[4], rb[4], rz4[4];
    float cp2 = 1.0f;
#pragma unroll
    for (int j = 0; j < 4; ++j) {
        float zlf = zl4[j];
        float dl  = (j < 3) ? (zl4[j + 1] - zlf)
                            : ((lane == 31) ? 0.0f : (znext - zlf));
        float z  = ex2(zlf * LOG2_10);
        rz4[j]   = rcpa(z);
        float x  = fmaf(dx, z, ox), y = fmaf(dy, z, oy), zz = fmaf(dz, z, oz);
        float n2 = fmaf(x, x, fmaf(y, y, zz * zz));
        float inv = rsqa(n2);
        float g   = 2.0f - inv;
        float f   = (n2 > 1.0f) ? g * inv : 1.0f;
        float ss  = (n2 > 1.0f) ? g * g   : n2;
        float sx = x * f, sy = y * f, sz = zz * f;
        float sig = 25.0f * ex2(ss * (-4.0f * LOG2E));
        rr[j] = rcpa(1.0f + ex2(-(sx + hx) * LOG2E));
        rg[j] = rcpa(1.0f + ex2(-(sy + hy) * LOG2E));
        rb[j] = rcpa(1.0f + ex2(-(sz + hz) * LOG2E));
        float o = ex2(sig * dl * (-LOG2E));   // dl==0 -> o==1 (last sample)
        om4[j] = o;
        al4[j] = 1.0f - o;
        cp2 *= o;
    }
    float fincl = cp2;
#pragma unroll
    for (int off = 1; off < 32; off <<= 1) {
        float v = __shfl_up_sync(FULL, fincl, off);
        if (lane >= off) fincl *= v;
    }
    float ftrans = __shfl_up_sync(FULL, fincl, 1);
    if (lane == 0) ftrans = 1.0f;

    const long long N3  = (long long)N * 3;
    const long long NWF = (long long)N * SFINE;
    float* __restrict__ out_img = out;
    float* __restrict__ out_wf  = out + N3;
    float* __restrict__ out_zv  = out + N3 + NWF;
    float* __restrict__ out_inv = out + N3 + 2 * NWF;

    float wf4[4], zv4[4];
    float imr = 0.0f, img = 0.0f, imb = 0.0f, invd = 0.0f, wsum = 0.0f;
#pragma unroll
    for (int j = 0; j < 4; ++j) {
        float wf = al4[j] * ftrans;
        ftrans *= om4[j];
        wf4[j] = wf;
        zv4[j] = (zl4[j] + 1.0f) * 0.5f;
        imr  += wf * rr[j];
        img  += wf * rg[j];
        imb  += wf * rb[j];
        invd += wf * rz4[j];
        wsum += wf;
    }
    if ((N & 3) == 0) {   // 16B-aligned rows -> vector stores
        ((float4*)out_wf)[(long long)ray * 32 + lane] =
            make_float4(wf4[0], wf4[1], wf4[2], wf4[3]);
        ((float4*)out_zv)[(long long)ray * 32 + lane] =
            make_float4(zv4[0], zv4[1], zv4[2], zv4[3]);
    } else {
#pragma unroll
        for (int j = 0; j < 4; ++j) {
            out_wf[(long long)ray * SFINE + lane * 4 + j] = wf4[j];
            out_zv[(long long)ray * SFINE + lane * 4 + j] = zv4[j];
        }
    }
#pragma unroll
    for (int off = 16; off > 0; off >>= 1) {
        imr  += __shfl_xor_sync(FULL, imr,  off);
        img  += __shfl_xor_sync(FULL, img,  off);
        imb  += __shfl_xor_sync(FULL, imb,  off);
        invd += __shfl_xor_sync(FULL, invd, off);
        wsum += __shfl_xor_sync(FULL, wsum, off);
    }
    if (lane == 0) {
        float rem = 1.0f - wsum;
        out_img[(long long)ray * 3 + 0] = fmaf(rem, bgx, imr);
        out_img[(long long)ray * 3 + 1] = fmaf(rem, bgy, img);
        out_img[(long long)ray * 3 + 2] = fmaf(rem, bgz, imb);
        out_inv[ray] = invd;
    }
}

extern "C" void kernel_launch(void* const* d_in, const int* in_sizes, int n_in,
                              void* d_out, int out_size) {
    const float* rays_o = (const float*)d_in[0];
    const float* rays_d = (const float*)d_in[1];
    const float* bg     = (const float*)d_in[2];
    float* out = (float*)d_out;
    int N = in_sizes[0] / 3;

    int blocks = (N + WPB - 1) / WPB;
    nerf_kernel<<<blocks, WPB * 32>>>(rays_o, rays_d, bg, out, N);
}

// round 7
// speedup vs baseline: 1.7659x; 1.0835x over previous
#include <cuda_runtime.h>

#define SCOARSE 256
#define SFINE   128
#define WPB     8
#define ZSTEP   0.0078125f          // exact log10 step of coarse grid
#define FLOORW  3.90625e-7f         // 1e-4 / 256
#define CSTEP   0.025952563f        // ZSTEP * log2(10)
#define SSC     (-5.7707801636f)    // -4 * log2(e)
#define EC      (-0.2817763752f)    // -25 * ZSTEP * log2(e)
#define EF      (-36.067376022f)    // -25 * log2(e)
#define NL2E    (-1.4426950409f)    // -log2(e)
#define LOG2_10 3.3219280949f

__device__ __forceinline__ float ex2(float x)  { float r; asm("ex2.approx.f32 %0, %1;"   : "=f"(r) : "f"(x)); return r; }
__device__ __forceinline__ float rcpa(float x) { float r; asm("rcp.approx.f32 %0, %1;"   : "=f"(r) : "f"(x)); return r; }
__device__ __forceinline__ float rsqa(float x) { float r; asm("rsqrt.approx.f32 %0, %1;" : "=f"(r) : "f"(x)); return r; }

__global__ __launch_bounds__(WPB * 32)
void nerf_kernel(const float* __restrict__ rays_o,
                 const float* __restrict__ rays_d,
                 const float* __restrict__ bg_color,
                 float* __restrict__ out, int N)
{
    const unsigned FULL = 0xffffffffu;
    const int lane = threadIdx.x & 31;
    const int w    = threadIdx.x >> 5;
    const int ray  = blockIdx.x * WPB + w;
    if (ray >= N) return;

    __shared__ float sB[WPB][SCOARSE];   // raw (unnormalized) CDF only

    // ---- ray setup ----
    float ox = rays_o[ray*3+0], oy = rays_o[ray*3+1], oz = rays_o[ray*3+2];
    float dx = rays_d[ray*3+0], dy = rays_d[ray*3+1], dz = rays_d[ray*3+2];
    {
        float inv = rsqa(dx*dx + dy*dy + dz*dz);
        dx *= inv; dy *= inv; dz *= inv;
    }

    // =================================================================
    // COARSE: 256 samples, 8 contiguous per lane. Only |contract|^2
    // matters; o = 1-alpha = ex2( EC * ex2(SSC*ss) ).
    // =================================================================
    float om8[8];
    float cp = 1.0f;
    float kbase = (float)(lane * 8 - 128) * CSTEP;
#pragma unroll
    for (int j = 0; j < 8; ++j) {
        float z  = ex2(kbase + (float)j * CSTEP);
        float x  = fmaf(dx, z, ox), y = fmaf(dy, z, oy), zz = fmaf(dz, z, oz);
        float n2 = fmaf(x, x, fmaf(y, y, zz * zz));
        float g  = 2.0f - rsqa(n2);
        float ss = (n2 > 1.0f) ? g * g : n2;
        float e1 = ex2(ss * SSC);
        float Ej = (j == 7 && lane == 31) ? 0.0f : EC;   // last delta = 0
        float o  = ex2(e1 * Ej);
        om8[j] = o;
        cp *= o;
    }
    // inclusive product scan of chunk products -> transmittance
    float incl = cp;
#pragma unroll
    for (int off = 1; off < 32; off <<= 1) {
        float v = __shfl_up_sync(FULL, incl, off);
        if (lane >= off) incl *= v;
    }
    float trans = __shfl_up_sync(FULL, incl, 1);
    if (lane == 0) trans = 1.0f;

    // weights in registers: w_j = (1-om_j) * trans_j
    float w8[8];
#pragma unroll
    for (int j = 0; j < 8; ++j) {
        w8[j] = (1.0f - om8[j]) * trans;
        trans *= om8[j];
    }
    // chunk-boundary neighbors (global edges -> 0, matching the pad)
    float wprev = __shfl_up_sync(FULL, w8[7], 1);
    float wnext = __shfl_down_sync(FULL, w8[0], 1);
    if (lane == 0)  wprev = 0.0f;
    if (lane == 31) wnext = 0.0f;

    // =================================================================
    // REWEIGHT in registers (maxblur + floor; segment scale 0.5 cancels
    // bit-exactly under normalization). In-place with rolling original.
    // =================================================================
    float csum = 0.0f;
    float prevO = wprev;
#pragma unroll
    for (int j = 0; j < 8; ++j) {
        float cur = w8[j];
        float nxt = (j < 7) ? w8[j + 1] : wnext;
        float v = fmaf(0.5f, fmaxf(prevO, cur) + fmaxf(cur, nxt), FLOORW);
        w8[j] = v;
        csum += v;
        prevO = cur;
    }
    // inclusive sum scan of chunk sums
    float incs = csum;
#pragma unroll
    for (int off = 1; off < 32; off <<= 1) {
        float v = __shfl_up_sync(FULL, incs, off);
        if (lane >= off) incs += v;
    }
    float total = __shfl_sync(FULL, incs, 31);
    float run   = __shfl_up_sync(FULL, incs, 1);
    if (lane == 0) run = 0.0f;
#pragma unroll
    for (int j = 0; j < 8; ++j) {
        run += w8[j];
        sB[w][lane * 8 + j] = run;        // raw cumsum; sB[..][255] == total
    }
    __syncwarp();

    // =================================================================
    // IMPORTANCE SAMPLING: u scaled by total (skip normalization).
    // Branchless 8-step upper-bound descent per sample.
    // =================================================================
    const float* cdf = sB[w];
    float ustep = total * (1.0f / 128.0f);
    float ubase = (float)(lane * 4) * ustep;
    float zl4[4];
#pragma unroll
    for (int j = 0; j < 4; ++j) {
        float u = fmaf((float)j + 0.5f, ustep, ubase);
        int lo = 0;
#pragma unroll
        for (int s = 128; s; s >>= 1)
            lo += (cdf[lo + s - 1] <= u) ? s : 0;
        // lo in [0,255]; width==0 only when lo==0
        int below = max(lo - 1, 0);
        float c0 = cdf[below], c1 = cdf[lo];
        float dn = c1 - c0;
        dn = (dn < 1e-8f) ? 1.0f : dn;           // only width-0 triggers
        float t  = (u - c0) * rcpa(dn);
        float wd = (lo != 0) ? ZSTEP : 0.0f;
        float b0 = (float)(below - 128) * ZSTEP;
        zl4[j] = fmaf(t, wd, b0);
    }

    // =================================================================
    // FINE: 4 contiguous samples per lane; deltas via regs + 1 shfl.
    // =================================================================
    float znext = __shfl_down_sync(FULL, zl4[0], 1);
    float mhx = NL2E * 0.1f * dx, mhy = NL2E * 0.1f * dy, mhz = NL2E * 0.1f * dz;

    float om4[4], rr[4], rg[4], rb[4], rz4[4];
    float cp2 = 1.0f;
#pragma unroll
    for (int j = 0; j < 4; ++j) {
        float zlf = zl4[j];
        float dl  = (j < 3) ? (zl4[j + 1] - zlf)
                            : ((lane == 31) ? 0.0f : (znext - zlf));
        float z   = ex2(zlf * LOG2_10);
        rz4[j]    = rcpa(z);
        float x   = fmaf(dx, z, ox), y = fmaf(dy, z, oy), zz = fmaf(dz, z, oz);
        float n2  = fmaf(x, x, fmaf(y, y, zz * zz));
        float inv = rsqa(n2);
        float g   = 2.0f - inv;
        bool  big = n2 > 1.0f;
        float ss  = big ? g * g   : n2;
        float f   = big ? g * inv : 1.0f;
        float mfc = f * NL2E;
        rr[j] = rcpa(1.0f + ex2(fmaf(x,  mfc, mhx)));
        rg[j] = rcpa(1.0f + ex2(fmaf(y,  mfc, mhy)));
        rb[j] = rcpa(1.0f + ex2(fmaf(zz, mfc, mhz)));
        float e1 = ex2(ss * SSC);
        float o  = ex2(e1 * (dl * EF));   // dl==0 -> o==1 (last sample)
        om4[j] = o;
        cp2 *= o;
    }
    float fincl = cp2;
#pragma unroll
    for (int off = 1; off < 32; off <<= 1) {
        float v = __shfl_up_sync(FULL, fincl, off);
        if (lane >= off) fincl *= v;
    }
    float ftrans = __shfl_up_sync(FULL, fincl, 1);
    if (lane == 0) ftrans = 1.0f;

    const long long N3  = (long long)N * 3;
    const long long NWF = (long long)N * SFINE;
    float* __restrict__ out_img = out;
    float* __restrict__ out_wf  = out + N3;
    float* __restrict__ out_zv  = out + N3 + NWF;
    float* __restrict__ out_inv = out + N3 + 2 * NWF;

    float wf4[4], zv4[4];
    float imr = 0.0f, img = 0.0f, imb = 0.0f, invd = 0.0f, wsum = 0.0f;
#pragma unroll
    for (int j = 0; j < 4; ++j) {
        float wf = (1.0f - om4[j]) * ftrans;
        ftrans *= om4[j];
        wf4[j] = wf;
        zv4[j] = fmaf(zl4[j], 0.5f, 0.5f);   // (zlf - lo)/(hi - lo)
        imr  = fmaf(wf, rr[j],  imr);
        img  = fmaf(wf, rg[j],  img);
        imb  = fmaf(wf, rb[j],  imb);
        invd = fmaf(wf, rz4[j], invd);
        wsum += wf;
    }
    if ((N & 3) == 0) {
        ((float4*)out_wf)[(long long)ray * 32 + lane] =
            make_float4(wf4[0], wf4[1], wf4[2], wf4[3]);
        ((float4*)out_zv)[(long long)ray * 32 + lane] =
            make_float4(zv4[0], zv4[1], zv4[2], zv4[3]);
    } else {
#pragma unroll
        for (int j = 0; j < 4; ++j) {
            out_wf[(long long)ray * SFINE + lane * 4 + j] = wf4[j];
            out_zv[(long long)ray * SFINE + lane * 4 + j] = zv4[j];
        }
    }
    // warp reductions (shfl butterfly — redux.f32 unsupported on sm_103)
#pragma unroll
    for (int off = 16; off > 0; off >>= 1) {
        imr  += __shfl_xor_sync(FULL, imr,  off);
        img  += __shfl_xor_sync(FULL, img,  off);
        imb  += __shfl_xor_sync(FULL, imb,  off);
        invd += __shfl_xor_sync(FULL, invd, off);
        wsum += __shfl_xor_sync(FULL, wsum, off);
    }
    if (lane == 0) {
        float rem = 1.0f - wsum;
        out_img[(long long)ray * 3 + 0] = fmaf(rem, bg_color[0], imr);
        out_img[(long long)ray * 3 + 1] = fmaf(rem, bg_color[1], img);
        out_img[(long long)ray * 3 + 2] = fmaf(rem, bg_color[2], imb);
        out_inv[ray] = invd;
    }
}

extern "C" void kernel_launch(void* const* d_in, const int* in_sizes, int n_in,
                              void* d_out, int out_size) {
    const float* rays_o = (const float*)d_in[0];
    const float* rays_d = (const float*)d_in[1];
    const float* bg     = (const float*)d_in[2];
    float* out = (float*)d_out;
    int N = in_sizes[0] / 3;

    int blocks = (N + WPB - 1) / WPB;
    nerf_kernel<<<blocks, WPB * 32>>>(rays_o, rays_d, bg, out, N);
}

// round 9
// speedup vs baseline: 1.9700x; 1.1156x over previous
#include <cuda_runtime.h>

#define SCOARSE 256
#define SFINE   128
#define WPB     8
#define ZSTEP   0.0078125f          // exact log10 step of coarse grid
#define HZSTEP  0.00390625f         // ZSTEP/2
#define FLOORW  3.90625e-7f         // 1e-4 / 256
#define CSTEP   0.025952563f        // ZSTEP * log2(10)
#define ZMUL    1.0181517217f       // 10^ZSTEP
#define SSC     (-5.7707801636f)    // -4 * log2(e)
#define EC      (-0.2817763752f)    // -25 * ZSTEP * log2(e)
#define EF      (-36.067376022f)    // -25 * log2(e)
#define LOG2_10 3.3219280949f

__device__ __forceinline__ float ex2(float x)   { float r; asm("ex2.approx.f32 %0, %1;"   : "=f"(r) : "f"(x)); return r; }
__device__ __forceinline__ float rcpa(float x)  { float r; asm("rcp.approx.f32 %0, %1;"   : "=f"(r) : "f"(x)); return r; }
__device__ __forceinline__ float rsqa(float x)  { float r; asm("rsqrt.approx.f32 %0, %1;" : "=f"(r) : "f"(x)); return r; }
__device__ __forceinline__ float tanha(float x) { float r; asm("tanh.approx.f32 %0, %1;"  : "=f"(r) : "f"(x)); return r; }

__global__ __launch_bounds__(WPB * 32)
void nerf_kernel(const float* __restrict__ rays_o,
                 const float* __restrict__ rays_d,
                 const float* __restrict__ bg_color,
                 float* __restrict__ out, int N)
{
    const unsigned FULL = 0xffffffffu;
    const int lane = threadIdx.x & 31;
    const int w    = threadIdx.x >> 5;
    const int ray  = blockIdx.x * WPB + w;
    if (ray >= N) return;

    __shared__ float sCD[WPB][SCOARSE + 1];   // padded raw cumsum: p[0]=0

    // ---- ray setup (broadcast loads; bg prefetched early) ----
    float ox = rays_o[ray*3+0], oy = rays_o[ray*3+1], oz = rays_o[ray*3+2];
    float dx = rays_d[ray*3+0], dy = rays_d[ray*3+1], dz = rays_d[ray*3+2];
    float bgx = bg_color[0], bgy = bg_color[1], bgz = bg_color[2];
    {
        float inv = rsqa(dx*dx + dy*dy + dz*dz);
        dx *= inv; dy *= inv; dz *= inv;
    }

    // =================================================================
    // COARSE: 256 samples, 8 contiguous per lane. z via multiplicative
    // recurrence; o = 1-alpha = ex2( EC * ex2(SSC*ss) ).
    // =================================================================
    float om8[8];
    float z = ex2((float)(lane * 8 - 128) * CSTEP);
#pragma unroll
    for (int j = 0; j < 8; ++j) {
        if (j) z *= ZMUL;
        float x  = fmaf(dx, z, ox), y = fmaf(dy, z, oy), zz = fmaf(dz, z, oz);
        float n2 = fmaf(x, x, fmaf(y, y, zz * zz));
        float g  = 2.0f - rsqa(n2);
        float ss = (n2 > 1.0f) ? g * g : n2;
        float e1 = ex2(ss * SSC);
        om8[j] = ex2(e1 * EC);
    }
    if (lane == 31) om8[7] = 1.0f;            // last delta = 0 -> alpha = 0
    float cp = ((om8[0]*om8[1])*(om8[2]*om8[3]))*((om8[4]*om8[5])*(om8[6]*om8[7]));

    // inclusive product scan of chunk products -> transmittance
    float incl = cp;
#pragma unroll
    for (int off = 1; off < 32; off <<= 1) {
        float v = __shfl_up_sync(FULL, incl, off);
        if (lane >= off) incl *= v;
    }
    float trans = __shfl_up_sync(FULL, incl, 1);
    if (lane == 0) trans = 1.0f;

    // weights in registers: w_j = (1-om_j) * trans_j
    float w8[8];
#pragma unroll
    for (int j = 0; j < 8; ++j) {
        w8[j] = (1.0f - om8[j]) * trans;
        trans *= om8[j];
    }
    // chunk-boundary neighbors (global edges -> 0, matching the pad)
    float wprev = __shfl_up_sync(FULL, w8[7], 1);
    float wnext = __shfl_down_sync(FULL, w8[0], 1);
    if (lane == 0)  wprev = 0.0f;
    if (lane == 31) wnext = 0.0f;

    // =================================================================
    // REWEIGHT in registers (maxblur + floor; segment scale 0.5 cancels
    // bit-exactly under normalization). In-place with rolling original.
    // =================================================================
    float csum = 0.0f;
    float prevO = wprev;
#pragma unroll
    for (int j = 0; j < 8; ++j) {
        float cur = w8[j];
        float nxt = (j < 7) ? w8[j + 1] : wnext;
        float v = fmaf(0.5f, fmaxf(prevO, cur) + fmaxf(cur, nxt), FLOORW);
        w8[j] = v;
        csum += v;
        prevO = cur;
    }
    // inclusive sum scan of chunk sums
    float incs = csum;
#pragma unroll
    for (int off = 1; off < 32; off <<= 1) {
        float v = __shfl_up_sync(FULL, incs, off);
        if (lane >= off) incs += v;
    }
    float total = __shfl_sync(FULL, incs, 31);
    float run   = __shfl_up_sync(FULL, incs, 1);
    if (lane == 0) { run = 0.0f; sCD[w][0] = 0.0f; }
#pragma unroll
    for (int j = 0; j < 8; ++j) {
        run += w8[j];
        sCD[w][lane * 8 + j + 1] = run;   // p[k+1] = cumsum_k; p[256] = total
    }
    __syncwarp();

    // =================================================================
    // IMPORTANCE SAMPLING on padded raw cumsum p[0..256].
    // Invariant after descent: p[lo] <= u < p[lo+1]  ->  dn > 0, t in [0,1).
    // =================================================================
    const float* p = sCD[w];
    float ustep = total * (1.0f / 128.0f);
    float ubase = (float)(lane * 4) * ustep;
    float q4[4], zl4[4];
#pragma unroll
    for (int j = 0; j < 4; ++j) {
        float u = fmaf((float)j + 0.5f, ustep, ubase);
        int lo = 0;
#pragma unroll
        for (int s = 128; s; s >>= 1)
            if (p[lo + s] <= u) lo += s;
        float c0 = p[lo], c1 = p[lo + 1];
        float t = (u - c0) * rcpa(c1 - c0);
        t = (lo == 0) ? 1.0f : t;             // degenerate first bin -> zlf = -1
        float q = (float)(lo - 129) + t;
        q4[j]  = q;
        zl4[j] = q * ZSTEP;
    }

    // =================================================================
    // FINE: 4 contiguous samples per lane; deltas via regs + 1 shfl.
    // Sigmoid via tanh:  sig(v) = 0.5*tanh(v/2) + 0.5.
    // =================================================================
    float znext = __shfl_down_sync(FULL, zl4[0], 1);
    float hbx = 0.05f * dx, hby = 0.05f * dy, hbz = 0.05f * dz;

    float om4[4], rr[4], rg[4], rb[4], rz4[4];
#pragma unroll
    for (int j = 0; j < 4; ++j) {
        float zlf = zl4[j];
        float dl  = (j < 3) ? (zl4[j + 1] - zlf)
                            : ((lane == 31) ? 0.0f : (znext - zlf));
        float zf  = ex2(zlf * LOG2_10);
        rz4[j]    = rcpa(zf);
        float x   = fmaf(dx, zf, ox), y = fmaf(dy, zf, oy), zz = fmaf(dz, zf, oz);
        float n2  = fmaf(x, x, fmaf(y, y, zz * zz));
        float inv = rsqa(n2);
        float g   = 2.0f - inv;
        bool  big = n2 > 1.0f;
        float ss  = big ? g * g   : n2;
        float f   = big ? g * inv : 1.0f;
        float hf  = 0.5f * f;
        rr[j] = fmaf(tanha(fmaf(x,  hf, hbx)), 0.5f, 0.5f);
        rg[j] = fmaf(tanha(fmaf(y,  hf, hby)), 0.5f, 0.5f);
        rb[j] = fmaf(tanha(fmaf(zz, hf, hbz)), 0.5f, 0.5f);
        float e1 = ex2(ss * SSC);
        om4[j] = ex2(e1 * (dl * EF));   // dl==0 -> o==1 (last sample)
    }
    float cp2 = (om4[0] * om4[1]) * (om4[2] * om4[3]);
    float fincl = cp2;
#pragma unroll
    for (int off = 1; off < 32; off <<= 1) {
        float v = __shfl_up_sync(FULL, fincl, off);
        if (lane >= off) fincl *= v;
    }
    float rem    = __shfl_sync(FULL, fincl, 31);   // = 1 - sum(wf) analytically
    float ftrans = __shfl_up_sync(FULL, fincl, 1);
    if (lane == 0) ftrans = 1.0f;

    const long long N3  = (long long)N * 3;
    const long long NWF = (long long)N * SFINE;
    float* __restrict__ out_img = out;
    float* __restrict__ out_wf  = out + N3;
    float* __restrict__ out_zv  = out + N3 + NWF;
    float* __restrict__ out_inv = out + N3 + 2 * NWF;

    float wf4[4], zv4[4];
    float imr = 0.0f, img = 0.0f, imb = 0.0f, invd = 0.0f;
#pragma unroll
    for (int j = 0; j < 4; ++j) {
        float wf = (1.0f - om4[j]) * ftrans;
        ftrans *= om4[j];
        wf4[j] = wf;
        zv4[j] = fmaf(q4[j], HZSTEP, 0.5f);   // (zlf - lo)/(hi - lo)
        imr  = fmaf(wf, rr[j],  imr);
        img  = fmaf(wf, rg[j],  img);
        imb  = fmaf(wf, rb[j],  imb);
        invd = fmaf(wf, rz4[j], invd);
    }
    if ((N & 3) == 0) {
        ((float4*)out_wf)[(long long)ray * 32 + lane] =
            make_float4(wf4[0], wf4[1], wf4[2], wf4[3]);
        ((float4*)out_zv)[(long long)ray * 32 + lane] =
            make_float4(zv4[0], zv4[1], zv4[2], zv4[3]);
    } else {
#pragma unroll
        for (int j = 0; j < 4; ++j) {
            out_wf[(long long)ray * SFINE + lane * 4 + j] = wf4[j];
            out_zv[(long long)ray * SFINE + lane * 4 + j] = zv4[j];
        }
    }
    // warp reductions (shfl butterfly — redux.f32 unsupported on sm_103)
#pragma unroll
    for (int off = 16; off > 0; off >>= 1) {
        imr  += __shfl_xor_sync(FULL, imr,  off);
        img  += __shfl_xor_sync(FULL, img,  off);
        imb  += __shfl_xor_sync(FULL, imb,  off);
        invd += __shfl_xor_sync(FULL, invd, off);
    }
    if (lane == 0) {
        out_img[(long long)ray * 3 + 0] = fmaf(rem, bgx, imr);
        out_img[(long long)ray * 3 + 1] = fmaf(rem, bgy, img);
        out_img[(long long)ray * 3 + 2] = fmaf(rem, bgz, imb);
        out_inv[ray] = invd;
    }
}

extern "C" void kernel_launch(void* const* d_in, const int* in_sizes, int n_in,
                              void* d_out, int out_size) {
    const float* rays_o = (const float*)d_in[0];
    const float* rays_d = (const float*)d_in[1];
    const float* bg     = (const float*)d_in[2];
    float* out = (float*)d_out;
    int N = in_sizes[0] / 3;

    int blocks = (N + WPB - 1) / WPB;
    nerf_kernel<<<blocks, WPB * 32>>>(rays_o, rays_d, bg, out, N);
}

// round 10
// speedup vs baseline: 1.9964x; 1.0134x over previous
#include <cuda_runtime.h>

#define SCOARSE 256
#define SFINE   128
#define WPB     8
#define ZSTEP   0.0078125f          // exact log10 step of coarse grid
#define HZSTEP  0.00390625f         // ZSTEP/2
#define FLOORW  3.90625e-7f         // 1e-4 / 256
#define CSTEP   0.025952563f        // ZSTEP * log2(10)
#define ZMUL    1.0181517217f       // 10^ZSTEP
#define SSC     (-5.7707801636f)    // -4 * log2(e)
#define LEC     (-1.8272376276f)    // log2(25*ZSTEP*log2(e))  -> f1 = ex2(ss*SSC + LEC) = -log2(1-alpha)
#define EF      (-36.067376022f)    // -25 * log2(e)
#define LOG2_10 3.3219280949f

__device__ __forceinline__ float ex2(float x)   { float r; asm("ex2.approx.f32 %0, %1;"   : "=f"(r) : "f"(x)); return r; }
__device__ __forceinline__ float rcpa(float x)  { float r; asm("rcp.approx.f32 %0, %1;"   : "=f"(r) : "f"(x)); return r; }
__device__ __forceinline__ float rsqa(float x)  { float r; asm("rsqrt.approx.f32 %0, %1;" : "=f"(r) : "f"(x)); return r; }
__device__ __forceinline__ float tanha(float x) { float r; asm("tanh.approx.f32 %0, %1;"  : "=f"(r) : "f"(x)); return r; }

__global__ __launch_bounds__(WPB * 32)
void nerf_kernel(const float* __restrict__ rays_o,
                 const float* __restrict__ rays_d,
                 const float* __restrict__ bg_color,
                 float* __restrict__ out, int N)
{
    const unsigned FULL = 0xffffffffu;
    const int lane = threadIdx.x & 31;
    const int w    = threadIdx.x >> 5;
    const int ray  = blockIdx.x * WPB + w;
    if (ray >= N) return;

    __shared__ float sCD[WPB][SCOARSE + 1];   // padded raw cumsum: p[0]=0

    // ---- ray setup ----
    float ox = rays_o[ray*3+0], oy = rays_o[ray*3+1], oz = rays_o[ray*3+2];
    float dx = rays_d[ray*3+0], dy = rays_d[ray*3+1], dz = rays_d[ray*3+2];
    float bgx = bg_color[0], bgy = bg_color[1], bgz = bg_color[2];
    {
        float inv = rsqa(dx*dx + dy*dy + dz*dz);
        dx *= inv; dy *= inv; dz *= inv;
    }

    // =================================================================
    // COARSE: 256 samples, 8 per lane. f1_k = -log2(1-alpha_k)
    //       = ex2(ss*SSC + LEC). Transmittance T_k = ex2(-prefix(f1)).
    // Weight w_k = T_k - T_{k+1} (== alpha_k * T_k exactly).
    // =================================================================
    float s8[8];
    float z   = ex2((float)(lane * 8 - 128) * CSTEP);
    float acc = 0.0f;
#pragma unroll
    for (int j = 0; j < 8; ++j) {
        if (j) z *= ZMUL;
        float x  = fmaf(dx, z, ox), y = fmaf(dy, z, oy), zz = fmaf(dz, z, oz);
        float n2 = fmaf(x, x, fmaf(y, y, zz * zz));
        float g  = 2.0f - rsqa(n2);
        float ss = (n2 > 1.0f) ? g * g : n2;
        float f1 = ex2(fmaf(ss, SSC, LEC));
        if (j == 7 && lane == 31) f1 = 0.0f;   // last delta = 0 -> alpha = 0
        acc += f1;
        s8[j] = acc;
    }
    // inclusive add-scan of chunk f1-sums -> global exclusive prefix G
    float incl = acc;
#pragma unroll
    for (int off = 1; off < 32; off <<= 1) {
        float v = __shfl_up_sync(FULL, incl, off);
        if (lane >= off) incl += v;
    }
    float G = __shfl_up_sync(FULL, incl, 1);
    if (lane == 0) G = 0.0f;

    float w8[8];
    float Tprev = ex2(-G);
#pragma unroll
    for (int j = 0; j < 8; ++j) {
        float T = ex2(-(G + s8[j]));
        w8[j] = Tprev - T;
        Tprev = T;
    }
    // chunk-boundary neighbors (global edges -> 0, matching the pad)
    float wprev = __shfl_up_sync(FULL, w8[7], 1);
    float wnext = __shfl_down_sync(FULL, w8[0], 1);
    if (lane == 0)  wprev = 0.0f;
    if (lane == 31) wnext = 0.0f;

    // =================================================================
    // REWEIGHT in registers (maxblur + floor; segment scale 0.5 cancels
    // bit-exactly under normalization). In-place with rolling original.
    // =================================================================
    float csum = 0.0f;
    float prevO = wprev;
#pragma unroll
    for (int j = 0; j < 8; ++j) {
        float cur = w8[j];
        float nxt = (j < 7) ? w8[j + 1] : wnext;
        float v = fmaf(0.5f, fmaxf(prevO, cur) + fmaxf(cur, nxt), FLOORW);
        w8[j] = v;
        csum += v;
        prevO = cur;
    }
    // inclusive sum scan of reweighted chunk sums; Ic kept for phase-1 search
    float Ic = csum;
#pragma unroll
    for (int off = 1; off < 32; off <<= 1) {
        float v = __shfl_up_sync(FULL, Ic, off);
        if (lane >= off) Ic += v;
    }
    float total = __shfl_sync(FULL, Ic, 31);
    float run   = __shfl_up_sync(FULL, Ic, 1);
    if (lane == 0) { run = 0.0f; sCD[w][0] = 0.0f; }
#pragma unroll
    for (int j = 0; j < 8; ++j) {
        run += w8[j];
        sCD[w][lane * 8 + j + 1] = run;   // p[k+1] = cumsum_k; p[256] ~= total
    }
    __syncwarp();

    // =================================================================
    // IMPORTANCE SAMPLING. Phase 1: 5-step binary search over the 32
    // register-resident chunk sums via SHFL.IDX (conflict-free).
    // Phase 2: 3-step LDS search within the 8-entry chunk.
    // =================================================================
    const float* p = sCD[w];
    float ustep = total * (1.0f / 128.0f);
    float ubase = (float)(lane * 4) * ustep;
    float q4[4], zl4[4];
#pragma unroll
    for (int j = 0; j < 4; ++j) {
        float u = fmaf((float)j + 0.5f, ustep, ubase);
        int c = 0;
#pragma unroll
        for (int s = 16; s; s >>= 1) {
            float v = __shfl_sync(FULL, Ic, c + s - 1);
            if (v <= u) c += s;
        }
        int lo = c * 8;
#pragma unroll
        for (int s = 4; s; s >>= 1)
            if (p[lo + s] <= u) lo += s;
        float c0 = p[lo], c1 = p[lo + 1];
        float t = (u - c0) * rcpa(c1 - c0);
        t = (lo == 0) ? 1.0f : t;             // degenerate first bin -> zlf = -1
        float q = (float)(lo - 129) + t;
        q4[j]  = q;
        zl4[j] = q * ZSTEP;
    }

    // =================================================================
    // FINE: 4 contiguous samples per lane; deltas via regs + 1 shfl.
    // Sigmoid via tanh:  sig(v) = 0.5*tanh(v/2) + 0.5.
    // =================================================================
    float znext = __shfl_down_sync(FULL, zl4[0], 1);
    float hbx = 0.05f * dx, hby = 0.05f * dy, hbz = 0.05f * dz;

    float om4[4], rr[4], rg[4], rb[4], rz4[4];
#pragma unroll
    for (int j = 0; j < 4; ++j) {
        float zlf = zl4[j];
        float dl  = (j < 3) ? (zl4[j + 1] - zlf)
                            : ((lane == 31) ? 0.0f : (znext - zlf));
        float zf  = ex2(zlf * LOG2_10);
        rz4[j]    = rcpa(zf);
        float x   = fmaf(dx, zf, ox), y = fmaf(dy, zf, oy), zz = fmaf(dz, zf, oz);
        float n2  = fmaf(x, x, fmaf(y, y, zz * zz));
        float inv = rsqa(n2);
        float g   = 2.0f - inv;
        bool  big = n2 > 1.0f;
        float ss  = big ? g * g   : n2;
        float f   = big ? g * inv : 1.0f;
        float hf  = 0.5f * f;
        rr[j] = fmaf(tanha(fmaf(x,  hf, hbx)), 0.5f, 0.5f);
        rg[j] = fmaf(tanha(fmaf(y,  hf, hby)), 0.5f, 0.5f);
        rb[j] = fmaf(tanha(fmaf(zz, hf, hbz)), 0.5f, 0.5f);
        float e1 = ex2(ss * SSC);
        om4[j] = ex2(e1 * (dl * EF));   // dl==0 -> o==1 (last sample)
    }
    float cp2 = (om4[0] * om4[1]) * (om4[2] * om4[3]);
    float fincl = cp2;
#pragma unroll
    for (int off = 1; off < 32; off <<= 1) {
        float v = __shfl_up_sync(FULL, fincl, off);
        if (lane >= off) fincl *= v;
    }
    float rem    = __shfl_sync(FULL, fincl, 31);   // = 1 - sum(wf) analytically
    float ftrans = __shfl_up_sync(FULL, fincl, 1);
    if (lane == 0) ftrans = 1.0f;

    const long long N3  = (long long)N * 3;
    const long long NWF = (long long)N * SFINE;
    float* __restrict__ out_img = out;
    float* __restrict__ out_wf  = out + N3;
    float* __restrict__ out_zv  = out + N3 + NWF;
    float* __restrict__ out_inv = out + N3 + 2 * NWF;

    float wf4[4], zv4[4];
    float imr = 0.0f, img = 0.0f, imb = 0.0f, invd = 0.0f;
#pragma unroll
    for (int j = 0; j < 4; ++j) {
        float wf = (1.0f - om4[j]) * ftrans;
        ftrans *= om4[j];
        wf4[j] = wf;
        zv4[j] = fmaf(q4[j], HZSTEP, 0.5f);   // (zlf - lo)/(hi - lo)
        imr  = fmaf(wf, rr[j],  imr);
        img  = fmaf(wf, rg[j],  img);
        imb  = fmaf(wf, rb[j],  imb);
        invd = fmaf(wf, rz4[j], invd);
    }
    if ((N & 3) == 0) {
        ((float4*)out_wf)[(long long)ray * 32 + lane] =
            make_float4(wf4[0], wf4[1], wf4[2], wf4[3]);
        ((float4*)out_zv)[(long long)ray * 32 + lane] =
            make_float4(zv4[0], zv4[1], zv4[2], zv4[3]);
    } else {
#pragma unroll
        for (int j = 0; j < 4; ++j) {
            out_wf[(long long)ray * SFINE + lane * 4 + j] = wf4[j];
            out_zv[(long long)ray * SFINE + lane * 4 + j] = zv4[j];
        }
    }
    // warp reductions (shfl butterfly — redux.f32 unsupported on sm_103)
#pragma unroll
    for (int off = 16; off > 0; off >>= 1) {
        imr  += __shfl_xor_sync(FULL, imr,  off);
        img  += __shfl_xor_sync(FULL, img,  off);
        imb  += __shfl_xor_sync(FULL, imb,  off);
        invd += __shfl_xor_sync(FULL, invd, off);
    }
    if (lane == 0) {
        out_img[(long long)ray * 3 + 0] = fmaf(rem, bgx, imr);
        out_img[(long long)ray * 3 + 1] = fmaf(rem, bgy, img);
        out_img[(long long)ray * 3 + 2] = fmaf(rem, bgz, imb);
        out_inv[ray] = invd;
    }
}

extern "C" void kernel_launch(void* const* d_in, const int* in_sizes, int n_in,
                              void* d_out, int out_size) {
    const float* rays_o = (const float*)d_in[0];
    const float* rays_d = (const float*)d_in[1];
    const float* bg     = (const float*)d_in[2];
    float* out = (float*)d_out;
    int N = in_sizes[0] / 3;

    int blocks = (N + WPB - 1) / WPB;
    nerf_kernel<<<blocks, WPB * 32>>>(rays_o, rays_d, bg, out, N);
}

// round 12
// speedup vs baseline: 2.0679x; 1.0358x over previous
#include <cuda_runtime.h>

#define SCOARSE 256
#define SFINE   128
#define WPB     8
#define ZSTEP   0.0078125f          // exact log10 step of coarse grid
#define HZSTEP  0.00390625f         // ZSTEP/2
#define FLOORW  3.90625e-7f         // 1e-4 / 256
#define CSTEP   0.025952563f        // ZSTEP * log2(10)
#define ZMUL    1.0181517217f       // 10^ZSTEP
#define SSC     (-5.7707801636f)    // -4 * log2(e)
#define EC      (-0.2817763752f)    // -25 * ZSTEP * log2(e): om-arg scale per q-unit
#define LOG2_10 3.3219280949f

__device__ __forceinline__ float ex2(float x)   { float r; asm("ex2.approx.f32 %0, %1;"   : "=f"(r) : "f"(x)); return r; }
__device__ __forceinline__ float rcpa(float x)  { float r; asm("rcp.approx.f32 %0, %1;"   : "=f"(r) : "f"(x)); return r; }
__device__ __forceinline__ float rsqa(float x)  { float r; asm("rsqrt.approx.f32 %0, %1;" : "=f"(r) : "f"(x)); return r; }
__device__ __forceinline__ float tanha(float x) { float r; asm("tanh.approx.f32 %0, %1;"  : "=f"(r) : "f"(x)); return r; }

__global__ __launch_bounds__(WPB * 32)
void nerf_kernel(const float* __restrict__ rays_o,
                 const float* __restrict__ rays_d,
                 const float* __restrict__ bg_color,
                 float* __restrict__ out, int N)
{
    const unsigned FULL = 0xffffffffu;
    const int lane = threadIdx.x & 31;
    const int w    = threadIdx.x >> 5;
    const int ray  = blockIdx.x * WPB + w;
    if (ray >= N) return;

    __shared__ float sCD[WPB][SCOARSE + 1];   // padded raw cumsum: p[0]=0

    // ---- ray setup ----
    float ox = rays_o[ray*3+0], oy = rays_o[ray*3+1], oz = rays_o[ray*3+2];
    float dx = rays_d[ray*3+0], dy = rays_d[ray*3+1], dz = rays_d[ray*3+2];
    float bgx = bg_color[0], bgy = bg_color[1], bgz = bg_color[2];
    {
        float inv = rsqa(dx*dx + dy*dy + dz*dz);
        dx *= inv; dy *= inv; dz *= inv;
    }
    // |o + d z|^2 = a + b z + z^2  (d normalized)
    float a = fmaf(ox, ox, fmaf(oy, oy, oz * oz));
    float od = fmaf(ox, dx, fmaf(oy, dy, oz * dz));
    float b = od + od;

    // =================================================================
    // COARSE: 256 samples, 8 per lane. n2 via the ray quadratic only.
    // om = 1-alpha = ex2( EC * ex2(SSC*ss) ). Product-scan transmittance
    // (accuracy: keeps cumulative error ~2^-22-scale, not arg-ulp-scale).
    // =================================================================
    float om8[8];
    float z = ex2((float)(lane * 8 - 128) * CSTEP);
#pragma unroll
    for (int j = 0; j < 8; ++j) {
        if (j) z *= ZMUL;
        float n2 = fmaf(z, z + b, a);
        float g  = 2.0f - rsqa(n2);
        float ss = (n2 > 1.0f) ? g * g : n2;
        float e1 = ex2(ss * SSC);
        om8[j] = ex2(e1 * EC);
    }
    if (lane == 31) om8[7] = 1.0f;            // last delta = 0 -> alpha = 0
    float cp = ((om8[0]*om8[1])*(om8[2]*om8[3]))*((om8[4]*om8[5])*(om8[6]*om8[7]));

    // inclusive product scan of chunk products -> transmittance
    float incl = cp;
#pragma unroll
    for (int off = 1; off < 32; off <<= 1) {
        float v = __shfl_up_sync(FULL, incl, off);
        if (lane >= off) incl *= v;
    }
    float trans = __shfl_up_sync(FULL, incl, 1);
    if (lane == 0) trans = 1.0f;

    float w8[8];
#pragma unroll
    for (int j = 0; j < 8; ++j) {
        w8[j] = (1.0f - om8[j]) * trans;
        trans *= om8[j];
    }
    // chunk-boundary neighbors (global edges -> 0, matching the pad)
    float wprev = __shfl_up_sync(FULL, w8[7], 1);
    float wnext = __shfl_down_sync(FULL, w8[0], 1);
    if (lane == 0)  wprev = 0.0f;
    if (lane == 31) wnext = 0.0f;

    // =================================================================
    // REWEIGHT in registers (maxblur + floor; segment scale 0.5 cancels
    // bit-exactly under normalization). In-place with rolling original.
    // =================================================================
    float csum = 0.0f;
    float prevO = wprev;
#pragma unroll
    for (int j = 0; j < 8; ++j) {
        float cur = w8[j];
        float nxt = (j < 7) ? w8[j + 1] : wnext;
        float v = fmaf(0.5f, fmaxf(prevO, cur) + fmaxf(cur, nxt), FLOORW);
        w8[j] = v;
        csum += v;
        prevO = cur;
    }
    // inclusive sum scan of reweighted chunk sums; Ic kept for phase-1 search
    float Ic = csum;
#pragma unroll
    for (int off = 1; off < 32; off <<= 1) {
        float v = __shfl_up_sync(FULL, Ic, off);
        if (lane >= off) Ic += v;
    }
    float total = __shfl_sync(FULL, Ic, 31);
    float run   = __shfl_up_sync(FULL, Ic, 1);
    if (lane == 0) { run = 0.0f; sCD[w][0] = 0.0f; }
#pragma unroll
    for (int j = 0; j < 8; ++j) {
        run += w8[j];
        sCD[w][lane * 8 + j + 1] = run;   // p[k+1] = cumsum_k; p[256] == total
    }
    __syncwarp();

    // =================================================================
    // IMPORTANCE SAMPLING. Phase 1: 5-step search over the 32 register-
    // resident chunk sums via SHFL.IDX; phase 2: 3-step LDS search.
    // Result kept in bin coordinate q (zlf = q * ZSTEP, never formed).
    // =================================================================
    const float* p = sCD[w];
    float ustep = total * (1.0f / 128.0f);
    float ubase = (float)(lane * 4) * ustep;
    float q4[4];
#pragma unroll
    for (int j = 0; j < 4; ++j) {
        float u = fmaf((float)j + 0.5f, ustep, ubase);
        int c = 0;
#pragma unroll
        for (int s = 16; s; s >>= 1) {
            float v = __shfl_sync(FULL, Ic, c + s - 1);
            if (v <= u) c += s;
        }
        int lo = c * 8;
#pragma unroll
        for (int s = 4; s; s >>= 1)
            if (p[lo + s] <= u) lo += s;
        float c0 = p[lo], c1 = p[lo + 1];
        float t = (u - c0) * rcpa(c1 - c0);
        t = (lo == 0) ? 1.0f : t;             // degenerate first bin -> q = -128
        q4[j] = (float)(lo - 129) + t;
    }

    // =================================================================
    // FINE: 4 contiguous samples per lane; deltas via regs + 1 shfl.
    // rgb accumulated as raw wf*tanh (0.5*x+0.5 folded into lane 0).
    // =================================================================
    float qnext = __shfl_down_sync(FULL, q4[0], 1);
    float hbx = 0.05f * dx, hby = 0.05f * dy, hbz = 0.05f * dz;

    float om4[4], tr4[4], tg4[4], tb4[4], rz4[4];
#pragma unroll
    for (int j = 0; j < 4; ++j) {
        float q  = q4[j];
        float dq = (j < 3) ? (q4[j + 1] - q)
                           : ((lane == 31) ? 0.0f : (qnext - q));
        float zf  = ex2(q * CSTEP);
        rz4[j]    = rcpa(zf);
        float x   = fmaf(dx, zf, ox), y = fmaf(dy, zf, oy), zz = fmaf(dz, zf, oz);
        float n2  = fmaf(zf, zf + b, a);
        float inv = rsqa(n2);
        float g   = 2.0f - inv;
        bool  big = n2 > 1.0f;
        float ss  = big ? g * g   : n2;
        float f   = big ? g * inv : 1.0f;
        float hf  = 0.5f * f;
        tr4[j] = tanha(fmaf(x,  hf, hbx));
        tg4[j] = tanha(fmaf(y,  hf, hby));
        tb4[j] = tanha(fmaf(zz, hf, hbz));
        float e1 = ex2(ss * SSC);
        om4[j] = ex2(e1 * (dq * EC));   // dq==0 -> om==1 (last sample)
    }
    float cp2 = (om4[0] * om4[1]) * (om4[2] * om4[3]);
    float fincl = cp2;
#pragma unroll
    for (int off = 1; off < 32; off <<= 1) {
        float v = __shfl_up_sync(FULL, fincl, off);
        if (lane >= off) fincl *= v;
    }
    float rem    = __shfl_sync(FULL, fincl, 31);   // = 1 - sum(wf) analytically
    float ftrans = __shfl_up_sync(FULL, fincl, 1);
    if (lane == 0) ftrans = 1.0f;

    const long long N3  = (long long)N * 3;
    const long long NWF = (long long)N * SFINE;
    float* __restrict__ out_img = out;
    float* __restrict__ out_wf  = out + N3;
    float* __restrict__ out_zv  = out + N3 + NWF;
    float* __restrict__ out_inv = out + N3 + 2 * NWF;

    float wf4[4], zv4[4];
    float str = 0.0f, stg = 0.0f, stb = 0.0f, invd = 0.0f;
#pragma unroll
    for (int j = 0; j < 4; ++j) {
        float wf = (1.0f - om4[j]) * ftrans;
        ftrans *= om4[j];
        wf4[j] = wf;
        zv4[j] = fmaf(q4[j], HZSTEP, 0.5f);   // (zlf - lo)/(hi - lo)
        str  = fmaf(wf, tr4[j], str);
        stg  = fmaf(wf, tg4[j], stg);
        stb  = fmaf(wf, tb4[j], stb);
        invd = fmaf(wf, rz4[j], invd);
    }
    if ((N & 3) == 0) {
        ((float4*)out_wf)[(long long)ray * 32 + lane] =
            make_float4(wf4[0], wf4[1], wf4[2], wf4[3]);
        ((float4*)out_zv)[(long long)ray * 32 + lane] =
            make_float4(zv4[0], zv4[1], zv4[2], zv4[3]);
    } else {
#pragma unroll
        for (int j = 0; j < 4; ++j) {
            out_wf[(long long)ray * SFINE + lane * 4 + j] = wf4[j];
            out_zv[(long long)ray * SFINE + lane * 4 + j] = zv4[j];
        }
    }
    // warp reductions (shfl butterfly — redux.f32 unsupported on sm_103)
#pragma unroll
    for (int off = 16; off > 0; off >>= 1) {
        str  += __shfl_xor_sync(FULL, str,  off);
        stg  += __shfl_xor_sync(FULL, stg,  off);
        stb  += __shfl_xor_sync(FULL, stb,  off);
        invd += __shfl_xor_sync(FULL, invd, off);
    }
    if (lane == 0) {
        float wsum = 1.0f - rem;
        float hw = 0.5f * wsum;
        // image_c = 0.5*sum(wf*tanh_c) + 0.5*wsum + rem*bg_c
        out_img[(long long)ray * 3 + 0] = fmaf(rem, bgx, fmaf(0.5f, str, hw));
        out_img[(long long)ray * 3 + 1] = fmaf(rem, bgy, fmaf(0.5f, stg, hw));
        out_img[(long long)ray * 3 + 2] = fmaf(rem, bgz, fmaf(0.5f, stb, hw));
        out_inv[ray] = invd;
    }
}

extern "C" void kernel_launch(void* const* d_in, const int* in_sizes, int n_in,
                              void* d_out, int out_size) {
    const float* rays_o = (const float*)d_in[0];
    const float* rays_d = (const float*)d_in[1];
    const float* bg     = (const float*)d_in[2];
    float* out = (float*)d_out;
    int N = in_sizes[0] / 3;

    int blocks = (N + WPB - 1) / WPB;
    nerf_kernel<<<blocks, WPB * 32>>>(rays_o, rays_d, bg, out, N);
}